// round 7
// baseline (speedup 1.0000x reference)
#include <cuda_runtime.h>
#include <cuda_bf16.h>
#include <cstdint>

#define B_ROWS 65536
#define DIM    256
#define NEMB   1024
#define MARGIN 1.5f
#define CAND_CAP 8

// ---------------------------------------------------------------------------
// Scratch (__device__ globals; no allocations)
// ---------------------------------------------------------------------------
__device__ float          g_xnorm[B_ROWS];
__device__ float          g_enorm[NEMB];
__device__ __nv_bfloat16  g_xb[(size_t)B_ROWS * DIM];
__device__ __nv_bfloat16  g_eb[(size_t)NEMB * DIM];
__device__ int            g_cnt[B_ROWS];
__device__ int            g_flag[B_ROWS];
__device__ int            g_cand[B_ROWS][CAND_CAP];

// ---------------------------------------------------------------------------
// PTX helpers (arch-agnostic sm_80 features only)
// ---------------------------------------------------------------------------
__device__ __forceinline__ uint32_t smem_u32(const void* p) {
    uint32_t a;
    asm("{ .reg .u64 t; cvta.to.shared.u64 t, %1; cvt.u32.u64 %0, t; }" : "=r"(a) : "l"(p));
    return a;
}
__device__ __forceinline__ void cp_async16(uint32_t dst, const void* src) {
    asm volatile("cp.async.cg.shared.global [%0], [%1], 16;" :: "r"(dst), "l"(src));
}
#define CP_COMMIT() asm volatile("cp.async.commit_group;" ::: "memory")
#define CP_WAIT(n)  asm volatile("cp.async.wait_group %0;" :: "n"(n) : "memory")

__device__ __forceinline__ void ldsm_x4(uint32_t* r, uint32_t addr) {
    asm volatile("ldmatrix.sync.aligned.m8n8.x4.shared.b16 {%0,%1,%2,%3}, [%4];"
                 : "=r"(r[0]), "=r"(r[1]), "=r"(r[2]), "=r"(r[3]) : "r"(addr) : "memory");
}
__device__ __forceinline__ void mma_bf16(float* c, const uint32_t* a, const uint32_t* b) {
    asm volatile("mma.sync.aligned.m16n8k16.row.col.f32.bf16.bf16.f32 "
                 "{%0,%1,%2,%3}, {%4,%5,%6,%7}, {%8,%9}, {%0,%1,%2,%3};"
                 : "+f"(c[0]), "+f"(c[1]), "+f"(c[2]), "+f"(c[3])
                 : "r"(a[0]), "r"(a[1]), "r"(a[2]), "r"(a[3]), "r"(b[0]), "r"(b[1]));
}
__device__ __forceinline__ void upd2(unsigned long long& k1, unsigned long long& k2,
                                     float d, int col) {
    unsigned long long key =
        ((unsigned long long)__float_as_uint(fmaxf(d, 0.f)) << 32) | (unsigned)col;
    if (key < k1) { k2 = k1; k1 = key; }
    else if (key < k2) { k2 = key; }
}

// ---------------------------------------------------------------------------
// Prep: fp32 -> bf16 conversion + exact fp32 row norms (one warp per row)
// ---------------------------------------------------------------------------
__global__ void prep_x_kernel(const float* __restrict__ x) {
    int m = blockIdx.x * 8 + (threadIdx.x >> 5);
    int lane = threadIdx.x & 31;
    const float4* xr = (const float4*)(x + (size_t)m * DIM);
    uint2* xb = (uint2*)(g_xb + (size_t)m * DIM);
    float s = 0.f;
#pragma unroll
    for (int i = 0; i < 2; i++) {
        int f = lane + i * 32;
        float4 v = xr[f];
        s += v.x * v.x + v.y * v.y + v.z * v.z + v.w * v.w;
        __nv_bfloat162 lo = __floats2bfloat162_rn(v.x, v.y);
        __nv_bfloat162 hi = __floats2bfloat162_rn(v.z, v.w);
        uint2 pk;
        pk.x = *(unsigned*)&lo; pk.y = *(unsigned*)&hi;
        xb[f] = pk;
    }
#pragma unroll
    for (int o = 16; o; o >>= 1) s += __shfl_xor_sync(0xFFFFFFFFu, s, o);
    if (lane == 0) g_xnorm[m] = s;
}

__global__ void prep_e_kernel(const float* __restrict__ e) {
    int m = blockIdx.x * 8 + (threadIdx.x >> 5);
    int lane = threadIdx.x & 31;
    const float4* er = (const float4*)(e + (size_t)m * DIM);
    uint2* eb = (uint2*)(g_eb + (size_t)m * DIM);
    float s = 0.f;
#pragma unroll
    for (int i = 0; i < 2; i++) {
        int f = lane + i * 32;
        float4 v = er[f];
        s += v.x * v.x + v.y * v.y + v.z * v.z + v.w * v.w;
        __nv_bfloat162 lo = __floats2bfloat162_rn(v.x, v.y);
        __nv_bfloat162 hi = __floats2bfloat162_rn(v.z, v.w);
        uint2 pk;
        pk.x = *(unsigned*)&lo; pk.y = *(unsigned*)&hi;
        eb[f] = pk;
    }
#pragma unroll
    for (int o = 16; o; o >>= 1) s += __shfl_xor_sync(0xFFFFFFFFu, s, o);
    if (lane == 0) g_enorm[m] = s;
}

// ---------------------------------------------------------------------------
// bf16 HMMA GEMM + online per-row argmin. NO distance matrix.
// Grid = 512 CTAs (one per 128-row M block); each CTA scans all 1024 codes
// (8 N-blocks, cp.async double-buffered B). Per (thread,row): two smallest
// approx keys in registers. Phase 2: smem atomicMin -> exact row min of the
// approx distances; threads append k1 cols within MARGIN to the row's cand
// list; if k2 is also within margin, the thread's 64-col subset is flagged
// (its 3rd-smallest is unknown -> output kernel rescans that subset exactly).
// Cand lists + flags (~3 MB) are the only global output.
// ---------------------------------------------------------------------------
#define SMEM_A_OFF    0
#define SMEM_B_OFF    65536
#define SMEM_EN_OFF   196608
#define SMEM_XN_OFF   200704
#define SMEM_MIN_OFF  201216
#define SMEM_CNT_OFF  202240
#define SMEM_FLAG_OFF 202752
#define SMEM_CAND_OFF 203264
#define GEMM_SMEM     207360

__global__ __launch_bounds__(256, 1) void gemm_argmin_kernel() {
    extern __shared__ char smem[];
    const uint32_t sb = smem_u32(smem);
    const int tid = threadIdx.x, lane = tid & 31, wid = tid >> 5;
    const int warp_m = wid >> 2, warp_n = wid & 3;
    const int m0 = blockIdx.x * 128;

    float* s_en = (float*)(smem + SMEM_EN_OFF);
    float* s_xn = (float*)(smem + SMEM_XN_OFF);
    unsigned long long* s_min = (unsigned long long*)(smem + SMEM_MIN_OFF);
    int* s_cnt  = (int*)(smem + SMEM_CNT_OFF);
    int* s_flag = (int*)(smem + SMEM_FLAG_OFF);
    int (*s_cand)[CAND_CAP] = (int(*)[CAND_CAP])(smem + SMEM_CAND_OFF);

    for (int i = tid; i < NEMB; i += 256) s_en[i] = g_enorm[i];
    if (tid < 128) {
        s_xn[tid]   = g_xnorm[m0 + tid];
        s_min[tid]  = 0xFFFFFFFFFFFFFFFFULL;
        s_cnt[tid]  = 0;
        s_flag[tid] = 0;
    }

    // A tile (once) + B blocks 0,1 (two cp.async groups)
    {
        const __nv_bfloat16* Asrc = g_xb + (size_t)m0 * DIM;
        for (int i = tid; i < 4096; i += 256) {
            int row = i >> 5, c = i & 31;
            cp_async16(sb + SMEM_A_OFF + row * 512 + ((c ^ (row & 7)) * 16),
                       Asrc + row * DIM + c * 8);
        }
        for (int i = tid; i < 4096; i += 256) {
            int row = i >> 5, c = i & 31;
            cp_async16(sb + SMEM_B_OFF + row * 512 + ((c ^ (row & 7)) * 16),
                       g_eb + row * DIM + c * 8);
        }
        CP_COMMIT();
        for (int i = tid; i < 4096; i += 256) {
            int row = i >> 5, c = i & 31;
            cp_async16(sb + SMEM_B_OFF + 65536 + row * 512 + ((c ^ (row & 7)) * 16),
                       g_eb + 128 * DIM + row * DIM + c * 8);
        }
        CP_COMMIT();
    }

    const int grp = lane >> 2, qc = (lane & 3) * 2;

    unsigned long long k1[4][2], k2[4][2];
#pragma unroll
    for (int t = 0; t < 4; t++) {
        k1[t][0] = k1[t][1] = 0xFFFFFFFFFFFFFFFFULL;
        k2[t][0] = k2[t][1] = 0xFFFFFFFFFFFFFFFFULL;
    }

#pragma unroll 1
    for (int nb = 0; nb < 8; nb++) {
        if (nb < 7) { CP_WAIT(1); } else { CP_WAIT(0); }
        __syncthreads();

        const uint32_t Abase = sb + SMEM_A_OFF;
        const uint32_t Bbase = sb + SMEM_B_OFF + (nb & 1) * 65536;

        float acc[4][4][4];
#pragma unroll
        for (int t = 0; t < 4; t++)
#pragma unroll
            for (int u = 0; u < 4; u++)
#pragma unroll
                for (int v = 0; v < 4; v++) acc[t][u][v] = 0.f;

#pragma unroll
        for (int ks = 0; ks < 16; ks++) {
            uint32_t a[4][4];
#pragma unroll
            for (int t = 0; t < 4; t++) {
                int row = warp_m * 64 + t * 16 + (lane & 15);
                int c = ks * 2 + (lane >> 4);
                ldsm_x4(a[t], Abase + row * 512 + ((c ^ (row & 7)) * 16));
            }
            uint32_t b[2][4];
#pragma unroll
            for (int p = 0; p < 2; p++) {
                int row = warp_n * 32 + p * 16 + (lane & 7) + ((lane >> 4) & 1) * 8;
                int c = ks * 2 + ((lane >> 3) & 1);
                ldsm_x4(b[p], Bbase + row * 512 + ((c ^ (row & 7)) * 16));
            }
#pragma unroll
            for (int t = 0; t < 4; t++)
#pragma unroll
                for (int u = 0; u < 4; u++)
                    mma_bf16(acc[t][u], a[t], &b[u >> 1][(u & 1) * 2]);
        }
        __syncthreads();   // all warps done reading this B buffer

        // Prefetch B block nb+2 into the freed buffer.
        if (nb + 2 < 8) {
            const __nv_bfloat16* Bsrc = g_eb + (size_t)(nb + 2) * 128 * DIM;
            uint32_t Bdst = sb + SMEM_B_OFF + (nb & 1) * 65536;
            for (int i = tid; i < 4096; i += 256) {
                int row = i >> 5, c = i & 31;
                cp_async16(Bdst + row * 512 + ((c ^ (row & 7)) * 16),
                           Bsrc + row * DIM + c * 8);
            }
            CP_COMMIT();
        }

        // Epilogue: distances -> register top-2 keys (no global traffic).
#pragma unroll
        for (int t = 0; t < 4; t++) {
            int r0 = warp_m * 64 + t * 16 + grp;
            float xn0 = s_xn[r0], xn1 = s_xn[r0 + 8];
#pragma unroll
            for (int u = 0; u < 4; u++) {
                int ng = nb * 128 + warp_n * 32 + u * 8 + qc;
                float en0 = s_en[ng], en1 = s_en[ng + 1];
                upd2(k1[t][0], k2[t][0], fmaf(-2.f, acc[t][u][0], xn0 + en0), ng);
                upd2(k1[t][0], k2[t][0], fmaf(-2.f, acc[t][u][1], xn0 + en1), ng + 1);
                upd2(k1[t][1], k2[t][1], fmaf(-2.f, acc[t][u][2], xn1 + en0), ng);
                upd2(k1[t][1], k2[t][1], fmaf(-2.f, acc[t][u][3], xn1 + en1), ng + 1);
            }
        }
    }

    // ---- Phase 2: exact row mins of approx distances ----
    __syncthreads();
#pragma unroll
    for (int t = 0; t < 4; t++)
#pragma unroll
        for (int h = 0; h < 2; h++) {
            int row = warp_m * 64 + t * 16 + h * 8 + grp;
            atomicMin(&s_min[row], k1[t][h]);
        }
    __syncthreads();

    // Candidates + subset flags.
    const int my_sub = warp_n * 4 + (lane & 3);
#pragma unroll
    for (int t = 0; t < 4; t++)
#pragma unroll
        for (int h = 0; h < 2; h++) {
            int row = warp_m * 64 + t * 16 + h * 8 + grp;
            float thr = __uint_as_float((unsigned)(s_min[row] >> 32)) + MARGIN;
            unsigned long long kk1 = k1[t][h], kk2 = k2[t][h];
            if (__uint_as_float((unsigned)(kk1 >> 32)) <= thr) {
                int pos = atomicAdd(&s_cnt[row], 1);
                if (pos < CAND_CAP) s_cand[row][pos] = (int)(kk1 & 0xFFFFFFFFULL);
            }
            if (__uint_as_float((unsigned)(kk2 >> 32)) <= thr)
                atomicOr(&s_flag[row], 1 << my_sub);   // 3rd-smallest unknown
        }
    __syncthreads();

    // Store per-row candidate data (~40 B/row).
    if (tid < 128) {
        int row = tid, m = m0 + row;
        int cnt = s_cnt[row];
        unsigned fl = (unsigned)s_flag[row];
        if (cnt > CAND_CAP) { fl = 0xFFFFu; cnt = 0; }   // rare: full exact rescan
        g_cnt[m]  = cnt;
        g_flag[m] = (int)fl;
#pragma unroll
        for (int i = 0; i < CAND_CAP; i++)
            g_cand[m][i] = (i < cnt) ? s_cand[row][i] : 0;
    }
}

// ---------------------------------------------------------------------------
// Refine + outputs. One warp per row (65536 warps): exact fp32 distances for
// the row's candidates (+ flagged 64-col subsets), true argmin, then write
// loss | quantized_st | onehot.
// ---------------------------------------------------------------------------
__global__ __launch_bounds__(256) void output_kernel(const float* __restrict__ x,
                                                     const float* __restrict__ Emb,
                                                     float* __restrict__ out) {
    const int wid = threadIdx.x >> 5, lane = threadIdx.x & 31;
    const int m = blockIdx.x * 8 + wid;

    const int cnt = g_cnt[m];
    unsigned fl = (unsigned)g_flag[m];

    const float4* xr = (const float4*)(x + (size_t)m * DIM);
    float4 xv0 = xr[lane], xv1 = xr[lane + 32];
    const float xn = g_xnorm[m];

    unsigned long long best = 0xFFFFFFFFFFFFFFFFULL;
    int phase = 0, c_i = 0, sub = 0, sub_i = 0;
    for (;;) {
        int col;
        if (phase == 0) {
            if (c_i >= cnt) { phase = 1; continue; }
            col = g_cand[m][c_i++];
        } else {
            if (sub_i == 0) {
                if (!fl) break;
                sub = __ffs(fl) - 1;
                fl &= fl - 1;
            }
            col = (sub_i >> 3) * 128 + (sub >> 2) * 32 + ((sub_i >> 1) & 3) * 8 +
                  (sub & 3) * 2 + (sub_i & 1);
            sub_i = (sub_i + 1) & 63;
        }
        const float4* er = (const float4*)(Emb + (size_t)col * DIM);
        float4 e0 = er[lane], e1 = er[lane + 32];
        float p = 0.f;
        p = fmaf(xv0.x, e0.x, p); p = fmaf(xv0.y, e0.y, p);
        p = fmaf(xv0.z, e0.z, p); p = fmaf(xv0.w, e0.w, p);
        p = fmaf(xv1.x, e1.x, p); p = fmaf(xv1.y, e1.y, p);
        p = fmaf(xv1.z, e1.z, p); p = fmaf(xv1.w, e1.w, p);
#pragma unroll
        for (int o = 16; o; o >>= 1) p += __shfl_xor_sync(0xFFFFFFFFu, p, o);
        float d = fmaxf(xn + g_enorm[col] - 2.f * p, 0.f);
        unsigned long long key =
            ((unsigned long long)__float_as_uint(d) << 32) | (unsigned)col;
        best = key < best ? key : best;
    }
    const unsigned idx = (unsigned)(best & 0xFFFFFFFFULL);

    // Outputs: loss | quantized_st | onehot.
    const float4* er = (const float4*)(Emb + (size_t)idx * DIM);
    float4* lossp = (float4*)out + (size_t)m * (DIM / 4);
    float4* qp    = (float4*)(out + (size_t)B_ROWS * DIM) + (size_t)m * (DIM / 4);
    float4* ohp   = (float4*)(out + 2ull * B_ROWS * DIM) + (size_t)m * (NEMB / 4);

#pragma unroll
    for (int i = 0; i < 2; i++) {
        int f = lane + i * 32;
        float4 xvv = (i == 0) ? xv0 : xv1;
        float4 ev = er[f];
        float4 dl, ls, q;
        dl.x = ev.x - xvv.x; dl.y = ev.y - xvv.y; dl.z = ev.z - xvv.z; dl.w = ev.w - xvv.w;
        q.x = xvv.x + dl.x; q.y = xvv.y + dl.y; q.z = xvv.z + dl.z; q.w = xvv.w + dl.w;
        ls.x = 0.25f * dl.x * dl.x; ls.y = 0.25f * dl.y * dl.y;
        ls.z = 0.25f * dl.z * dl.z; ls.w = 0.25f * dl.w * dl.w;
        lossp[f] = ls;
        qp[f] = q;
    }
    const unsigned hot4 = idx >> 2, comp = idx & 3;
#pragma unroll
    for (int i = lane; i < NEMB / 4; i += 32) {
        float4 z = make_float4(0.f, 0.f, 0.f, 0.f);
        if ((unsigned)i == hot4) ((float*)&z)[comp] = 1.0f;
        ohp[i] = z;
    }
}

// ---------------------------------------------------------------------------
extern "C" void kernel_launch(void* const* d_in, const int* in_sizes, int n_in,
                              void* d_out, int out_size) {
    const float* x;
    const float* e;
    if (in_sizes[0] == B_ROWS * DIM) {
        x = (const float*)d_in[0];
        e = (const float*)d_in[1];
    } else {
        x = (const float*)d_in[1];
        e = (const float*)d_in[0];
    }
    float* out = (float*)d_out;

    static bool attr_done = false;
    if (!attr_done) {
        cudaFuncSetAttribute(gemm_argmin_kernel,
                             cudaFuncAttributeMaxDynamicSharedMemorySize, GEMM_SMEM);
        attr_done = true;
    }

    prep_x_kernel<<<B_ROWS / 8, 256>>>(x);
    prep_e_kernel<<<NEMB / 8, 256>>>(e);

    gemm_argmin_kernel<<<B_ROWS / 128, 256, GEMM_SMEM>>>();

    output_kernel<<<B_ROWS / 8, 256>>>(x, e, out);
}

// round 8
// speedup vs baseline: 1.7763x; 1.7763x over previous
#include <cuda_runtime.h>
#include <cuda_bf16.h>
#include <cuda_fp16.h>
#include <cstdint>

#define B_ROWS 65536
#define DIM    256
#define NEMB   1024
#define MARGIN 2.0f
#define NSPLIT 2
#define NB_PER 4          // 8 N-blocks / NSPLIT

// ---------------------------------------------------------------------------
// Scratch (__device__ globals; no allocations)
// ---------------------------------------------------------------------------
__device__ float          g_xnorm[B_ROWS];
__device__ float          g_enorm[NEMB];
__device__ __nv_bfloat16  g_xb[(size_t)B_ROWS * DIM];
__device__ __nv_bfloat16  g_eb[(size_t)NEMB * DIM];
__device__ __half         g_dist_h[(size_t)B_ROWS * NEMB];   // 134 MB approx distances

// ---------------------------------------------------------------------------
// PTX helpers (arch-agnostic sm_80 features only)
// ---------------------------------------------------------------------------
__device__ __forceinline__ uint32_t smem_u32(const void* p) {
    uint32_t a;
    asm("{ .reg .u64 t; cvta.to.shared.u64 t, %1; cvt.u32.u64 %0, t; }" : "=r"(a) : "l"(p));
    return a;
}
__device__ __forceinline__ void cp_async16(uint32_t dst, const void* src) {
    asm volatile("cp.async.cg.shared.global [%0], [%1], 16;" :: "r"(dst), "l"(src));
}
#define CP_COMMIT() asm volatile("cp.async.commit_group;" ::: "memory")
#define CP_WAIT(n)  asm volatile("cp.async.wait_group %0;" :: "n"(n) : "memory")

__device__ __forceinline__ void ldsm_x4(uint32_t* r, uint32_t addr) {
    asm volatile("ldmatrix.sync.aligned.m8n8.x4.shared.b16 {%0,%1,%2,%3}, [%4];"
                 : "=r"(r[0]), "=r"(r[1]), "=r"(r[2]), "=r"(r[3]) : "r"(addr) : "memory");
}
__device__ __forceinline__ void mma_bf16(float* c, const uint32_t* a, const uint32_t* b) {
    asm volatile("mma.sync.aligned.m16n8k16.row.col.f32.bf16.bf16.f32 "
                 "{%0,%1,%2,%3}, {%4,%5,%6,%7}, {%8,%9}, {%0,%1,%2,%3};"
                 : "+f"(c[0]), "+f"(c[1]), "+f"(c[2]), "+f"(c[3])
                 : "r"(a[0]), "r"(a[1]), "r"(a[2]), "r"(a[3]), "r"(b[0]), "r"(b[1]));
}

// ---------------------------------------------------------------------------
// Prep: fp32 -> bf16 + exact fp32 row norms. One warp per row; blocks past
// the x range handle the embedding rows.
// ---------------------------------------------------------------------------
__global__ void prep_kernel(const float* __restrict__ x, const float* __restrict__ e) {
    int gw = blockIdx.x * 8 + (threadIdx.x >> 5);
    int lane = threadIdx.x & 31;
    const float* src;
    uint2* dst;
    float* nrm;
    if (gw < B_ROWS) {
        src = x + (size_t)gw * DIM;
        dst = (uint2*)(g_xb + (size_t)gw * DIM);
        nrm = g_xnorm + gw;
    } else {
        int m = gw - B_ROWS;
        if (m >= NEMB) return;
        src = e + (size_t)m * DIM;
        dst = (uint2*)(g_eb + (size_t)m * DIM);
        nrm = g_enorm + m;
    }
    const float4* sr = (const float4*)src;
    float s = 0.f;
#pragma unroll
    for (int i = 0; i < 2; i++) {
        int f = lane + i * 32;
        float4 v = sr[f];
        s += v.x * v.x + v.y * v.y + v.z * v.z + v.w * v.w;
        __nv_bfloat162 lo = __floats2bfloat162_rn(v.x, v.y);
        __nv_bfloat162 hi = __floats2bfloat162_rn(v.z, v.w);
        uint2 pk;
        pk.x = *(unsigned*)&lo; pk.y = *(unsigned*)&hi;
        dst[f] = pk;
    }
#pragma unroll
    for (int o = 16; o; o >>= 1) s += __shfl_xor_sync(0xFFFFFFFFu, s, o);
    if (lane == 0) *nrm = s;
}

// ---------------------------------------------------------------------------
// bf16 HMMA GEMM: approx distances -> fp16.
// Grid = (512, 2): 128-row M block x 512-code N half. 1024 CTAs -> wave
// quantization 7/6.92 (vs 4/3.46 at 512 CTAs). A tile SMEM-resident;
// 4 N-blocks of 128 codes, cp.async double-buffered B.
// 8 warps in 2(M) x 4(N), warp tile 64x32, mma.m16n8k16 bf16 -> fp32.
// SMEM rows = 512 B; 16B chunk c stored at c ^ (row & 7) (conflict-free).
// ---------------------------------------------------------------------------
#define SMEM_A_OFF  0
#define SMEM_B_OFF  65536
#define SMEM_EN_OFF 196608
#define SMEM_XN_OFF 200704
#define GEMM_SMEM   201216

__global__ __launch_bounds__(256, 1) void gemm_dist_kernel() {
    extern __shared__ char smem[];
    const uint32_t sb = smem_u32(smem);
    const int tid = threadIdx.x, lane = tid & 31, wid = tid >> 5;
    const int warp_m = wid >> 2, warp_n = wid & 3;
    const int m0 = blockIdx.x * 128;
    const int n0 = blockIdx.y * (NEMB / NSPLIT);     // 0 or 512

    float* s_en = (float*)(smem + SMEM_EN_OFF);      // this half's 512 norms
    float* s_xn = (float*)(smem + SMEM_XN_OFF);
    for (int i = tid; i < NEMB / NSPLIT; i += 256) s_en[i] = g_enorm[n0 + i];
    if (tid < 128) s_xn[tid] = g_xnorm[m0 + tid];

    // A tile (once) + B blocks 0,1 of this half (two cp.async groups)
    {
        const __nv_bfloat16* Asrc = g_xb + (size_t)m0 * DIM;
        const __nv_bfloat16* Bsrc = g_eb + (size_t)n0 * DIM;
        for (int i = tid; i < 4096; i += 256) {
            int row = i >> 5, c = i & 31;
            cp_async16(sb + SMEM_A_OFF + row * 512 + ((c ^ (row & 7)) * 16),
                       Asrc + row * DIM + c * 8);
        }
        for (int i = tid; i < 4096; i += 256) {
            int row = i >> 5, c = i & 31;
            cp_async16(sb + SMEM_B_OFF + row * 512 + ((c ^ (row & 7)) * 16),
                       Bsrc + row * DIM + c * 8);
        }
        CP_COMMIT();
        for (int i = tid; i < 4096; i += 256) {
            int row = i >> 5, c = i & 31;
            cp_async16(sb + SMEM_B_OFF + 65536 + row * 512 + ((c ^ (row & 7)) * 16),
                       Bsrc + 128 * DIM + row * DIM + c * 8);
        }
        CP_COMMIT();
    }

    const int grp = lane >> 2, qc = (lane & 3) * 2;

#pragma unroll 1
    for (int nb = 0; nb < NB_PER; nb++) {
        if (nb < NB_PER - 1) { CP_WAIT(1); } else { CP_WAIT(0); }
        __syncthreads();

        const uint32_t Abase = sb + SMEM_A_OFF;
        const uint32_t Bbase = sb + SMEM_B_OFF + (nb & 1) * 65536;

        float acc[4][4][4];
#pragma unroll
        for (int t = 0; t < 4; t++)
#pragma unroll
            for (int u = 0; u < 4; u++)
#pragma unroll
                for (int v = 0; v < 4; v++) acc[t][u][v] = 0.f;

#pragma unroll
        for (int ks = 0; ks < 16; ks++) {
            uint32_t a[4][4];
#pragma unroll
            for (int t = 0; t < 4; t++) {
                int row = warp_m * 64 + t * 16 + (lane & 15);
                int c = ks * 2 + (lane >> 4);
                ldsm_x4(a[t], Abase + row * 512 + ((c ^ (row & 7)) * 16));
            }
            uint32_t b[2][4];
#pragma unroll
            for (int p = 0; p < 2; p++) {
                int row = warp_n * 32 + p * 16 + (lane & 7) + ((lane >> 4) & 1) * 8;
                int c = ks * 2 + ((lane >> 3) & 1);
                ldsm_x4(b[p], Bbase + row * 512 + ((c ^ (row & 7)) * 16));
            }
#pragma unroll
            for (int t = 0; t < 4; t++)
#pragma unroll
                for (int u = 0; u < 4; u++)
                    mma_bf16(acc[t][u], a[t], &b[u >> 1][(u & 1) * 2]);
        }
        __syncthreads();   // all warps done reading this B buffer

        // Prefetch B block nb+2 of this half into the freed buffer.
        if (nb + 2 < NB_PER) {
            const __nv_bfloat16* Bsrc = g_eb + (size_t)(n0 + (nb + 2) * 128) * DIM;
            uint32_t Bdst = sb + SMEM_B_OFF + (nb & 1) * 65536;
            for (int i = tid; i < 4096; i += 256) {
                int row = i >> 5, c = i & 31;
                cp_async16(Bdst + row * 512 + ((c ^ (row & 7)) * 16),
                           Bsrc + row * DIM + c * 8);
            }
            CP_COMMIT();
        }

        // Epilogue: d = xn + en - 2*dot -> fp16 (overlaps with prefetch).
#pragma unroll
        for (int t = 0; t < 4; t++) {
            int r0 = warp_m * 64 + t * 16 + grp;
            int r1 = r0 + 8;
            float xn0 = s_xn[r0], xn1 = s_xn[r1];
#pragma unroll
            for (int u = 0; u < 4; u++) {
                int nl = nb * 128 + warp_n * 32 + u * 8 + qc;   // local col in half
                int ng = n0 + nl;                               // global col
                float en0 = s_en[nl], en1 = s_en[nl + 1];
                float d0 = fmaf(-2.f, acc[t][u][0], xn0 + en0);
                float d1 = fmaf(-2.f, acc[t][u][1], xn0 + en1);
                float d2 = fmaf(-2.f, acc[t][u][2], xn1 + en0);
                float d3 = fmaf(-2.f, acc[t][u][3], xn1 + en1);
                *(__half2*)(g_dist_h + (size_t)(m0 + r0) * NEMB + ng) = __floats2half2_rn(d0, d1);
                *(__half2*)(g_dist_h + (size_t)(m0 + r1) * NEMB + ng) = __floats2half2_rn(d2, d3);
            }
        }
    }
}

// ---------------------------------------------------------------------------
// Select + refine + outputs. One warp per row (identical to round-3 winner).
// ---------------------------------------------------------------------------
__global__ __launch_bounds__(256) void select_output_kernel(const float* __restrict__ x,
                                                            const float* __restrict__ Emb,
                                                            float* __restrict__ out) {
    const int wid = threadIdx.x >> 5, lane = threadIdx.x & 31;
    const int m = blockIdx.x * 8 + wid;

    __shared__ int s_cnt[8];
    __shared__ int s_cand[8][16];
    if (lane == 0) s_cnt[wid] = 0;
    __syncwarp();

    // Row's 1024 fp16 distances: 4 x uint4 per lane (8 halves each).
    const uint4* dp = (const uint4*)(g_dist_h + (size_t)m * NEMB);
    uint4 dv[4];
    unsigned long long bk = 0xFFFFFFFFFFFFFFFFULL;
#pragma unroll
    for (int i = 0; i < 4; i++) {
        int f = lane + i * 32;
        dv[i] = dp[f];
#pragma unroll
        for (int c = 0; c < 4; c++) {
            float2 f2 = __half22float2(((const __half2*)&dv[i])[c]);
            int col = f * 8 + c * 2;
            float v0 = fmaxf(f2.x, 0.f), v1 = fmaxf(f2.y, 0.f);
            unsigned long long k0 = ((unsigned long long)__float_as_uint(v0) << 32) | (unsigned)col;
            unsigned long long k1 = ((unsigned long long)__float_as_uint(v1) << 32) | (unsigned)(col + 1);
            bk = k0 < bk ? k0 : bk;
            bk = k1 < bk ? k1 : bk;
        }
    }
#pragma unroll
    for (int o = 16; o; o >>= 1) {
        unsigned long long t = __shfl_xor_sync(0xFFFFFFFFu, bk, o);
        bk = t < bk ? t : bk;
    }
    const float thr = __uint_as_float((unsigned)(bk >> 32)) + MARGIN;

    // Collect candidates within margin.
#pragma unroll
    for (int i = 0; i < 4; i++) {
        int f = lane + i * 32;
#pragma unroll
        for (int c = 0; c < 4; c++) {
            float2 f2 = __half22float2(((const __half2*)&dv[i])[c]);
            int col = f * 8 + c * 2;
            if (f2.x <= thr) {
                int pos = atomicAdd(&s_cnt[wid], 1);
                if (pos < 16) s_cand[wid][pos] = col;
            }
            if (f2.y <= thr) {
                int pos = atomicAdd(&s_cnt[wid], 1);
                if (pos < 16) s_cand[wid][pos] = col + 1;
            }
        }
    }
    __syncwarp();
    const int cnt = s_cnt[wid];
    const bool fallback = cnt > 16;      // rare; exact full scan
    const int ncand = fallback ? NEMB : cnt;

    const float4* xr = (const float4*)(x + (size_t)m * DIM);
    float4 xv0 = xr[lane], xv1 = xr[lane + 32];
    const float xn = g_xnorm[m];

    unsigned long long best = 0xFFFFFFFFFFFFFFFFULL;
    for (int t = 0; t < ncand; t++) {
        const int col = fallback ? t : s_cand[wid][t];
        const float4* er = (const float4*)(Emb + (size_t)col * DIM);
        float4 e0 = er[lane], e1 = er[lane + 32];
        float p = 0.f;
        p = fmaf(xv0.x, e0.x, p); p = fmaf(xv0.y, e0.y, p);
        p = fmaf(xv0.z, e0.z, p); p = fmaf(xv0.w, e0.w, p);
        p = fmaf(xv1.x, e1.x, p); p = fmaf(xv1.y, e1.y, p);
        p = fmaf(xv1.z, e1.z, p); p = fmaf(xv1.w, e1.w, p);
#pragma unroll
        for (int o = 16; o; o >>= 1) p += __shfl_xor_sync(0xFFFFFFFFu, p, o);
        float d = fmaxf(xn + g_enorm[col] - 2.f * p, 0.f);
        unsigned long long key = ((unsigned long long)__float_as_uint(d) << 32) | (unsigned)col;
        best = key < best ? key : best;
    }
    const unsigned idx = (unsigned)(best & 0xFFFFFFFFULL);

    // Outputs: loss | quantized_st | onehot.
    const float4* er = (const float4*)(Emb + (size_t)idx * DIM);
    float4* lossp = (float4*)out + (size_t)m * (DIM / 4);
    float4* qp    = (float4*)(out + (size_t)B_ROWS * DIM) + (size_t)m * (DIM / 4);
    float4* ohp   = (float4*)(out + 2ull * B_ROWS * DIM) + (size_t)m * (NEMB / 4);

#pragma unroll
    for (int i = 0; i < 2; i++) {
        int f = lane + i * 32;
        float4 xvv = (i == 0) ? xv0 : xv1;
        float4 ev = er[f];
        float4 dl, ls, q;
        dl.x = ev.x - xvv.x; dl.y = ev.y - xvv.y; dl.z = ev.z - xvv.z; dl.w = ev.w - xvv.w;
        q.x = xvv.x + dl.x; q.y = xvv.y + dl.y; q.z = xvv.z + dl.z; q.w = xvv.w + dl.w;
        ls.x = 0.25f * dl.x * dl.x; ls.y = 0.25f * dl.y * dl.y;
        ls.z = 0.25f * dl.z * dl.z; ls.w = 0.25f * dl.w * dl.w;
        lossp[f] = ls;
        qp[f] = q;
    }
    const unsigned hot4 = idx >> 2, comp = idx & 3;
#pragma unroll
    for (int i = lane; i < NEMB / 4; i += 32) {
        float4 z = make_float4(0.f, 0.f, 0.f, 0.f);
        if ((unsigned)i == hot4) ((float*)&z)[comp] = 1.0f;
        ohp[i] = z;
    }
}

// ---------------------------------------------------------------------------
extern "C" void kernel_launch(void* const* d_in, const int* in_sizes, int n_in,
                              void* d_out, int out_size) {
    const float* x;
    const float* e;
    if (in_sizes[0] == B_ROWS * DIM) {
        x = (const float*)d_in[0];
        e = (const float*)d_in[1];
    } else {
        x = (const float*)d_in[1];
        e = (const float*)d_in[0];
    }
    float* out = (float*)d_out;

    static bool attr_done = false;
    if (!attr_done) {
        cudaFuncSetAttribute(gemm_dist_kernel,
                             cudaFuncAttributeMaxDynamicSharedMemorySize, GEMM_SMEM);
        attr_done = true;
    }

    prep_kernel<<<(B_ROWS + NEMB) / 8, 256>>>(x, e);

    dim3 grid(B_ROWS / 128, NSPLIT);   // 512 x 2 = 1024 CTAs
    gemm_dist_kernel<<<grid, 256, GEMM_SMEM>>>();

    select_output_kernel<<<B_ROWS / 8, 256>>>(x, e, out);
}